// round 1
// baseline (speedup 1.0000x reference)
#include <cuda_runtime.h>
#include <math.h>

// Problem constants
#define B_  8
#define L_  2048
#define C_  512
#define CI_ 256

// Scratch (allocation-free: __device__ globals)
__device__ float g_xproj[(size_t)B_ * L_ * CI_];                 // 16.8 MB
__device__ float g_yproj[(size_t)B_ * L_ * CI_];                 // 16.8 MB
__device__ float g_oproj[(size_t)B_ * L_ * C_];                  // 33.5 MB
__device__ float g_scores[(size_t)B_ * L_ * L_];                 // 134 MB (attn in-place)

// SGEMM tiling
#define BM 128
#define BN 128
#define BK 8
#define TM 8
#define TN 8
// 256 threads/block, 16x16 thread grid, 8x8 microtile each.

// ---------------------------------------------------------------------------
// Kernel 1: projections. C[M,N] = A[M,K] @ W[K,N] + bias[N]
// sel: 0 -> g_xproj, 1 -> g_yproj, 2 -> g_oproj
// ---------------------------------------------------------------------------
__global__ __launch_bounds__(256) void gemm_proj(
    const float* __restrict__ A, const float* __restrict__ W,
    const float* __restrict__ bias, int N, int K, int sel)
{
    __shared__ float As[BK][BM];
    __shared__ float Bs[BK][BN];

    float* C = (sel == 0) ? g_xproj : (sel == 1) ? g_yproj : g_oproj;

    const int tid = threadIdx.x;
    const int m0 = blockIdx.y * BM;
    const int n0 = blockIdx.x * BN;
    const int ty = tid >> 4, tx = tid & 15;

    // A-load mapping: each thread loads a float4 along K
    const int am = tid >> 1;            // 0..127 (row in tile)
    const int ak = (tid & 1) * 4;       // 0 or 4
    // B-load mapping (B is [K,N] row-major): contiguous float4 along N
    const int bk = tid >> 5;            // 0..7
    const int bn = (tid & 31) * 4;      // 0..124

    float acc[TM][TN] = {};

    for (int k0 = 0; k0 < K; k0 += BK) {
        float4 av = *reinterpret_cast<const float4*>(&A[(size_t)(m0 + am) * K + k0 + ak]);
        As[ak + 0][am] = av.x; As[ak + 1][am] = av.y;
        As[ak + 2][am] = av.z; As[ak + 3][am] = av.w;
        float4 bv = *reinterpret_cast<const float4*>(&W[(size_t)(k0 + bk) * N + n0 + bn]);
        *reinterpret_cast<float4*>(&Bs[bk][bn]) = bv;
        __syncthreads();
        #pragma unroll
        for (int k = 0; k < BK; ++k) {
            float a[TM], b[TN];
            #pragma unroll
            for (int i = 0; i < TM; ++i) a[i] = As[k][ty * TM + i];
            #pragma unroll
            for (int j = 0; j < TN; ++j) b[j] = Bs[k][tx * TN + j];
            #pragma unroll
            for (int i = 0; i < TM; ++i)
                #pragma unroll
                for (int j = 0; j < TN; ++j)
                    acc[i][j] += a[i] * b[j];
        }
        __syncthreads();
    }

    #pragma unroll
    for (int i = 0; i < TM; ++i) {
        const int m = m0 + ty * TM + i;
        #pragma unroll
        for (int j = 0; j < TN; ++j) {
            const int n = n0 + tx * TN + j;
            C[(size_t)m * N + n] = acc[i][j] + bias[n];
        }
    }
}

// ---------------------------------------------------------------------------
// Kernel 2: scores[b] = x_proj[b] @ y_proj[b]^T  (NT GEMM, M=N=2048, K=256)
// ---------------------------------------------------------------------------
__global__ __launch_bounds__(256) void gemm_nt_scores()
{
    __shared__ float As[BK][BM];
    __shared__ float Bs[BK][BN];

    const int bz = blockIdx.z;
    const float* A  = g_xproj + (size_t)bz * L_ * CI_;
    const float* Bm = g_yproj + (size_t)bz * L_ * CI_;
    float* C = g_scores + (size_t)bz * L_ * L_;
    const int K = CI_;
    const int N = L_;

    const int tid = threadIdx.x;
    const int m0 = blockIdx.y * BM;
    const int n0 = blockIdx.x * BN;
    const int ty = tid >> 4, tx = tid & 15;

    const int am = tid >> 1;
    const int ak = (tid & 1) * 4;

    float acc[TM][TN] = {};

    for (int k0 = 0; k0 < K; k0 += BK) {
        float4 av = *reinterpret_cast<const float4*>(&A[(size_t)(m0 + am) * K + k0 + ak]);
        As[ak + 0][am] = av.x; As[ak + 1][am] = av.y;
        As[ak + 2][am] = av.z; As[ak + 3][am] = av.w;
        // B is [N,K] row-major: same scatter pattern as A
        float4 bv = *reinterpret_cast<const float4*>(&Bm[(size_t)(n0 + am) * K + k0 + ak]);
        Bs[ak + 0][am] = bv.x; Bs[ak + 1][am] = bv.y;
        Bs[ak + 2][am] = bv.z; Bs[ak + 3][am] = bv.w;
        __syncthreads();
        #pragma unroll
        for (int k = 0; k < BK; ++k) {
            float a[TM], b[TN];
            #pragma unroll
            for (int i = 0; i < TM; ++i) a[i] = As[k][ty * TM + i];
            #pragma unroll
            for (int j = 0; j < TN; ++j) b[j] = Bs[k][tx * TN + j];
            #pragma unroll
            for (int i = 0; i < TM; ++i)
                #pragma unroll
                for (int j = 0; j < TN; ++j)
                    acc[i][j] += a[i] * b[j];
        }
        __syncthreads();
    }

    #pragma unroll
    for (int i = 0; i < TM; ++i) {
        const int m = m0 + ty * TM + i;
        #pragma unroll
        for (int j = 0; j < TN; ++j) {
            const int n = n0 + tx * TN + j;
            C[(size_t)m * N + n] = acc[i][j];
        }
    }
}

// ---------------------------------------------------------------------------
// Kernel 3: softmax over the BATCH axis (8 values per (l,m)), in-place.
// Read-once / write-once, values kept in registers.
// ---------------------------------------------------------------------------
__global__ __launch_bounds__(256) void softmax_batch()
{
    const size_t idx = (size_t)blockIdx.x * 256 + threadIdx.x;   // 0 .. L*L-1
    const size_t stride = (size_t)L_ * L_;

    float v[B_];
    float mx = -INFINITY;
    #pragma unroll
    for (int b = 0; b < B_; ++b) {
        v[b] = g_scores[b * stride + idx];
        mx = fmaxf(mx, v[b]);
    }
    float sum = 0.f;
    #pragma unroll
    for (int b = 0; b < B_; ++b) {
        v[b] = expf(v[b] - mx);
        sum += v[b];
    }
    const float inv = 1.f / sum;
    #pragma unroll
    for (int b = 0; b < B_; ++b) {
        g_scores[b * stride + idx] = v[b] * inv;
    }
}

// ---------------------------------------------------------------------------
// Kernel 4: out[b] = inputs[b] + attn[b] @ o_proj[b]  (NN, M=2048, N=512, K=2048)
// ---------------------------------------------------------------------------
__global__ __launch_bounds__(256) void gemm_nn_out(
    const float* __restrict__ inp, float* __restrict__ out)
{
    __shared__ float As[BK][BM];
    __shared__ float Bs[BK][BN];

    const int bz = blockIdx.z;
    const float* A  = g_scores + (size_t)bz * L_ * L_;   // [L, L]
    const float* Bm = g_oproj  + (size_t)bz * L_ * C_;   // [L, C]
    const int K = L_;
    const int N = C_;

    const int tid = threadIdx.x;
    const int m0 = blockIdx.y * BM;
    const int n0 = blockIdx.x * BN;
    const int ty = tid >> 4, tx = tid & 15;

    const int am = tid >> 1;
    const int ak = (tid & 1) * 4;
    const int bk = tid >> 5;
    const int bn = (tid & 31) * 4;

    float acc[TM][TN] = {};

    for (int k0 = 0; k0 < K; k0 += BK) {
        float4 av = *reinterpret_cast<const float4*>(&A[(size_t)(m0 + am) * K + k0 + ak]);
        As[ak + 0][am] = av.x; As[ak + 1][am] = av.y;
        As[ak + 2][am] = av.z; As[ak + 3][am] = av.w;
        float4 bv = *reinterpret_cast<const float4*>(&Bm[(size_t)(k0 + bk) * N + n0 + bn]);
        *reinterpret_cast<float4*>(&Bs[bk][bn]) = bv;
        __syncthreads();
        #pragma unroll
        for (int k = 0; k < BK; ++k) {
            float a[TM], b[TN];
            #pragma unroll
            for (int i = 0; i < TM; ++i) a[i] = As[k][ty * TM + i];
            #pragma unroll
            for (int j = 0; j < TN; ++j) b[j] = Bs[k][tx * TN + j];
            #pragma unroll
            for (int i = 0; i < TM; ++i)
                #pragma unroll
                for (int j = 0; j < TN; ++j)
                    acc[i][j] += a[i] * b[j];
        }
        __syncthreads();
    }

    const size_t batch_off = (size_t)bz * L_ * C_;
    #pragma unroll
    for (int i = 0; i < TM; ++i) {
        const int m = m0 + ty * TM + i;
        #pragma unroll
        for (int j = 0; j < TN; ++j) {
            const int n = n0 + tx * TN + j;
            const size_t o = batch_off + (size_t)m * N + n;
            out[o] = inp[o] + acc[i][j];
        }
    }
}

// ---------------------------------------------------------------------------
// Launch: inputs, Wx, bx, Wy, by, Wo, bo  (metadata order)
// ---------------------------------------------------------------------------
extern "C" void kernel_launch(void* const* d_in, const int* in_sizes, int n_in,
                              void* d_out, int out_size)
{
    const float* inputs = (const float*)d_in[0];
    const float* Wx = (const float*)d_in[1];
    const float* bx = (const float*)d_in[2];
    const float* Wy = (const float*)d_in[3];
    const float* by = (const float*)d_in[4];
    const float* Wo = (const float*)d_in[5];
    const float* bo = (const float*)d_in[6];
    float* out = (float*)d_out;

    const dim3 blk(256);
    const int M = B_ * L_;   // 16384

    // 1) projections: inputs[M,512] @ W[512,{256,256,512}]
    gemm_proj<<<dim3(CI_ / BN, M / BM), blk>>>(inputs, Wx, bx, CI_, C_, 0);
    gemm_proj<<<dim3(CI_ / BN, M / BM), blk>>>(inputs, Wy, by, CI_, C_, 1);
    gemm_proj<<<dim3(C_  / BN, M / BM), blk>>>(inputs, Wo, bo, C_,  C_, 2);

    // 2) scores[b] = x_proj[b] @ y_proj[b]^T
    gemm_nt_scores<<<dim3(L_ / BN, L_ / BM, B_), blk>>>();

    // 3) softmax over batch axis, in place
    softmax_batch<<<(L_ * L_) / 256, blk>>>();

    // 4) out = inputs + attn @ o_proj
    gemm_nn_out<<<dim3(C_ / BN, L_ / BM, B_), blk>>>(inputs, out);
}

// round 3
// speedup vs baseline: 2.1216x; 2.1216x over previous
#include <cuda_runtime.h>
#include <cuda_bf16.h>
#include <cstdint>
#include <math.h>

// ---------------------------------------------------------------------------
// Problem constants
// ---------------------------------------------------------------------------
#define B_  8
#define L_  2048
#define C_  512
#define CI_ 256
#define MT_ 16384   // B_*L_

// ---------------------------------------------------------------------------
// Scratch (__device__ globals; allocation-free)
// ---------------------------------------------------------------------------
__device__ float g_xproj [(size_t)B_ * L_ * CI_];   // [b][l][i]
__device__ float g_yproj [(size_t)B_ * L_ * CI_];   // [b][l][i]
__device__ float g_oprojT[(size_t)C_ * MT_];        // [c][b*l]  (transposed)
__device__ float g_scores[(size_t)B_ * L_ * L_];    // [b][l][m] (attn in place)
__device__ float g_WxT[CI_ * C_];                   // [i][c]
__device__ float g_WyT[CI_ * C_];
__device__ float g_WoT[C_ * C_];                    // [d][c]

// ---------------------------------------------------------------------------
// bf16 helpers
// ---------------------------------------------------------------------------
__device__ __forceinline__ uint32_t pack_bf2(__nv_bfloat16 a, __nv_bfloat16 b) {
    return (uint32_t)__bfloat16_as_ushort(a) |
           ((uint32_t)__bfloat16_as_ushort(b) << 16);
}

// Split a float4 into bf16 hi pair-words and bf16 lo (residual) pair-words.
__device__ __forceinline__ void split4(float4 v, uint32_t& h0, uint32_t& h1,
                                       uint32_t& l0, uint32_t& l1) {
    __nv_bfloat16 hx = __float2bfloat16_rn(v.x);
    __nv_bfloat16 hy = __float2bfloat16_rn(v.y);
    __nv_bfloat16 hz = __float2bfloat16_rn(v.z);
    __nv_bfloat16 hw = __float2bfloat16_rn(v.w);
    __nv_bfloat16 lx = __float2bfloat16_rn(v.x - __bfloat162float(hx));
    __nv_bfloat16 ly = __float2bfloat16_rn(v.y - __bfloat162float(hy));
    __nv_bfloat16 lz = __float2bfloat16_rn(v.z - __bfloat162float(hz));
    __nv_bfloat16 lw = __float2bfloat16_rn(v.w - __bfloat162float(hw));
    h0 = pack_bf2(hx, hy); h1 = pack_bf2(hz, hw);
    l0 = pack_bf2(lx, ly); l1 = pack_bf2(lz, lw);
}

// mma.sync m16n8k16 row.col f32.bf16.bf16.f32 (sm_80+, compiles for compute_103)
__device__ __forceinline__ void mma_bf16(float* d, const uint32_t* a, const uint32_t* b) {
    asm volatile(
        "mma.sync.aligned.m16n8k16.row.col.f32.bf16.bf16.f32 "
        "{%0,%1,%2,%3}, {%4,%5,%6,%7}, {%8,%9}, {%0,%1,%2,%3};"
        : "+f"(d[0]), "+f"(d[1]), "+f"(d[2]), "+f"(d[3])
        : "r"(a[0]), "r"(a[1]), "r"(a[2]), "r"(a[3]), "r"(b[0]), "r"(b[1]));
}

// ---------------------------------------------------------------------------
// 3-term split-bf16 GEMM: D[M,N] = A[M,K] @ B[N,K]^T (both K-major).
// Block tile 128x128, K-chunk 32, 256 threads (8 warps: 4(M) x 2(N)),
// warp tile 32x64, mma m16n8k16, fp32 accumulate, 2-stage SMEM ring.
// EPI: 0=store, 1=+bias[n], 2=+bias[m], 3=+residual (layout of C)
//
// SMEM per stage: Ah, Al, Bh, Bl each [128 rows][40 bf16] (80B stride, 8-pad)
//   = 10240 B each, 40960 B/stage, 2 stages = 81920 B.
// ---------------------------------------------------------------------------
#define ROWB 80                       // bytes per smem row
#define ROW32 20                      // b32 words per smem row
#define TILE_B 10240                  // bytes per (matrix, half) tile
#define STAGE_B 40960
#define SMEM_GEMM_TOTAL (2 * STAGE_B)

template<int KTOT, int EPI>
__global__ __launch_bounds__(256) void gemm3x(
    const float* __restrict__ Ap, long long sA,
    const float* __restrict__ Bp, long long sB, int ldB,
    float* __restrict__ Cp, long long sC, int ldC,
    const float* __restrict__ aux, long long sAux)
{
    extern __shared__ char smem[];

    const int tid  = threadIdx.x;
    const int wid  = tid >> 5;
    const int lane = tid & 31;
    const int g    = lane >> 2;       // 0..7
    const int t    = lane & 3;        // 0..3
    const int wm   = (wid & 3) * 32;  // warp M offset in tile
    const int wn   = (wid >> 2) * 64; // warp N offset in tile

    const int bz = blockIdx.z;
    const int m0 = blockIdx.y * 128;
    const int n0 = blockIdx.x * 128;
    const float* A  = Ap + (size_t)bz * sA;
    const float* Bb = Bp + (size_t)bz * sB;

    float acc[2][8][4] = {};
    float4 ra[4], rb[4];

    constexpr int NC = KTOT / 32;

    // ---- prologue: load + stage chunk 0 ----
    {
        #pragma unroll
        for (int i = 0; i < 4; ++i) {
            const int idx = tid + 256 * i;
            const int row = idx >> 3, kq = idx & 7;
            ra[i] = *(const float4*)&A [(size_t)(m0 + row) * KTOT + kq * 4];
            rb[i] = *(const float4*)&Bb[(size_t)(n0 + row) * ldB  + kq * 4];
        }
        char* Ah = smem;            char* Al = smem + TILE_B;
        char* Bh = smem + 2*TILE_B; char* Bl = smem + 3*TILE_B;
        #pragma unroll
        for (int i = 0; i < 4; ++i) {
            const int idx = tid + 256 * i;
            const int row = idx >> 3, kq = idx & 7;
            const int off = row * ROWB + kq * 8;
            uint32_t h0, h1, l0, l1;
            split4(ra[i], h0, h1, l0, l1);
            *(uint2*)(Ah + off) = make_uint2(h0, h1);
            *(uint2*)(Al + off) = make_uint2(l0, l1);
            split4(rb[i], h0, h1, l0, l1);
            *(uint2*)(Bh + off) = make_uint2(h0, h1);
            *(uint2*)(Bl + off) = make_uint2(l0, l1);
        }
    }

    // ---- main loop ----
    for (int kc = 0; kc < NC; ++kc) {
        __syncthreads();

        // issue LDGs for next chunk early
        if (kc + 1 < NC) {
            const int k0 = (kc + 1) * 32;
            #pragma unroll
            for (int i = 0; i < 4; ++i) {
                const int idx = tid + 256 * i;
                const int row = idx >> 3, kq = idx & 7;
                ra[i] = *(const float4*)&A [(size_t)(m0 + row) * KTOT + k0 + kq * 4];
                rb[i] = *(const float4*)&Bb[(size_t)(n0 + row) * ldB  + k0 + kq * 4];
            }
        }

        // compute from buffer kc&1
        {
            const char* base = smem + (size_t)(kc & 1) * STAGE_B;
            const uint32_t* Ah32 = (const uint32_t*)(base);
            const uint32_t* Al32 = (const uint32_t*)(base + TILE_B);
            const uint32_t* Bh32 = (const uint32_t*)(base + 2*TILE_B);
            const uint32_t* Bl32 = (const uint32_t*)(base + 3*TILE_B);

            #pragma unroll
            for (int ks = 0; ks < 2; ++ks) {
                const int kb = ks * 8;
                uint32_t aH[2][4], aL[2][4];
                #pragma unroll
                for (int mi = 0; mi < 2; ++mi) {
                    const int r = wm + mi * 16 + g;
                    aH[mi][0] = Ah32[(r    ) * ROW32 + kb + t];
                    aH[mi][1] = Ah32[(r + 8) * ROW32 + kb + t];
                    aH[mi][2] = Ah32[(r    ) * ROW32 + kb + t + 4];
                    aH[mi][3] = Ah32[(r + 8) * ROW32 + kb + t + 4];
                    aL[mi][0] = Al32[(r    ) * ROW32 + kb + t];
                    aL[mi][1] = Al32[(r + 8) * ROW32 + kb + t];
                    aL[mi][2] = Al32[(r    ) * ROW32 + kb + t + 4];
                    aL[mi][3] = Al32[(r + 8) * ROW32 + kb + t + 4];
                }
                #pragma unroll
                for (int nj = 0; nj < 8; ++nj) {
                    const int n = wn + nj * 8 + g;
                    uint32_t bH[2], bL[2];
                    bH[0] = Bh32[n * ROW32 + kb + t];
                    bH[1] = Bh32[n * ROW32 + kb + t + 4];
                    bL[0] = Bl32[n * ROW32 + kb + t];
                    bL[1] = Bl32[n * ROW32 + kb + t + 4];
                    #pragma unroll
                    for (int mi = 0; mi < 2; ++mi) {
                        mma_bf16(acc[mi][nj], aH[mi], bH);
                        mma_bf16(acc[mi][nj], aH[mi], bL);
                        mma_bf16(acc[mi][nj], aL[mi], bH);
                    }
                }
            }
        }

        // stage next chunk into the other buffer
        if (kc + 1 < NC) {
            char* base = smem + (size_t)((kc + 1) & 1) * STAGE_B;
            char* Ah = base;            char* Al = base + TILE_B;
            char* Bh = base + 2*TILE_B; char* Bl = base + 3*TILE_B;
            #pragma unroll
            for (int i = 0; i < 4; ++i) {
                const int idx = tid + 256 * i;
                const int row = idx >> 3, kq = idx & 7;
                const int off = row * ROWB + kq * 8;
                uint32_t h0, h1, l0, l1;
                split4(ra[i], h0, h1, l0, l1);
                *(uint2*)(Ah + off) = make_uint2(h0, h1);
                *(uint2*)(Al + off) = make_uint2(l0, l1);
                split4(rb[i], h0, h1, l0, l1);
                *(uint2*)(Bh + off) = make_uint2(h0, h1);
                *(uint2*)(Bl + off) = make_uint2(l0, l1);
            }
        }
    }

    // ---- epilogue ----
    float* Cb = Cp + (size_t)bz * sC;
    float biasr[4];
    if (EPI == 2) {
        #pragma unroll
        for (int mi = 0; mi < 2; ++mi) {
            biasr[mi*2 + 0] = aux[m0 + wm + mi*16 + g    ];
            biasr[mi*2 + 1] = aux[m0 + wm + mi*16 + g + 8];
        }
    }
    const float* R = (EPI == 3) ? (aux + (size_t)bz * sAux) : nullptr;

    #pragma unroll
    for (int mi = 0; mi < 2; ++mi) {
        const int r0 = m0 + wm + mi * 16 + g;
        const int r1 = r0 + 8;
        #pragma unroll
        for (int nj = 0; nj < 8; ++nj) {
            const int col = n0 + wn + nj * 8 + 2 * t;
            float2 v0 = make_float2(acc[mi][nj][0], acc[mi][nj][1]);
            float2 v1 = make_float2(acc[mi][nj][2], acc[mi][nj][3]);
            if (EPI == 1) {
                const float2 bb = *(const float2*)&aux[col];
                v0.x += bb.x; v0.y += bb.y; v1.x += bb.x; v1.y += bb.y;
            } else if (EPI == 2) {
                v0.x += biasr[mi*2];     v0.y += biasr[mi*2];
                v1.x += biasr[mi*2 + 1]; v1.y += biasr[mi*2 + 1];
            } else if (EPI == 3) {
                const float2 q0 = *(const float2*)&R[(size_t)r0 * ldC + col];
                const float2 q1 = *(const float2*)&R[(size_t)r1 * ldC + col];
                v0.x += q0.x; v0.y += q0.y; v1.x += q1.x; v1.y += q1.y;
            }
            *(float2*)&Cb[(size_t)r0 * ldC + col] = v0;
            *(float2*)&Cb[(size_t)r1 * ldC + col] = v1;
        }
    }
}

// ---------------------------------------------------------------------------
// 32x32 tiled transpose: src[R][Cc] -> dst[Cc][R]
// ---------------------------------------------------------------------------
__global__ void transpose32(const float* __restrict__ src, float* __restrict__ dst,
                            int R, int Cc)
{
    __shared__ float tbuf[32][33];
    const int bx = blockIdx.x * 32;
    const int by = blockIdx.y * 32;
    const int x = threadIdx.x, y = threadIdx.y;   // 32 x 8
    #pragma unroll
    for (int d = 0; d < 32; d += 8)
        tbuf[y + d][x] = src[(size_t)(by + y + d) * Cc + bx + x];
    __syncthreads();
    #pragma unroll
    for (int d = 0; d < 32; d += 8)
        dst[(size_t)(bx + y + d) * R + by + x] = tbuf[x][y + d];
}

// ---------------------------------------------------------------------------
// Softmax over the batch axis (8 values per (l,m)), in-place
// ---------------------------------------------------------------------------
__global__ __launch_bounds__(256) void softmax_batch()
{
    const size_t idx = (size_t)blockIdx.x * 256 + threadIdx.x;   // 0..L*L-1
    const size_t stride = (size_t)L_ * L_;
    float v[B_];
    float mx = -INFINITY;
    #pragma unroll
    for (int b = 0; b < B_; ++b) {
        v[b] = g_scores[b * stride + idx];
        mx = fmaxf(mx, v[b]);
    }
    float sum = 0.f;
    #pragma unroll
    for (int b = 0; b < B_; ++b) { v[b] = expf(v[b] - mx); sum += v[b]; }
    const float inv = 1.f / sum;
    #pragma unroll
    for (int b = 0; b < B_; ++b) g_scores[b * stride + idx] = v[b] * inv;
}

// ---------------------------------------------------------------------------
// Launch: inputs, Wx, bx, Wy, by, Wo, bo
// ---------------------------------------------------------------------------
extern "C" void kernel_launch(void* const* d_in, const int* in_sizes, int n_in,
                              void* d_out, int out_size)
{
    const float* inputs = (const float*)d_in[0];
    const float* Wx = (const float*)d_in[1];
    const float* bx = (const float*)d_in[2];
    const float* Wy = (const float*)d_in[3];
    const float* by = (const float*)d_in[4];
    const float* Wo = (const float*)d_in[5];
    const float* bo = (const float*)d_in[6];
    float* out = (float*)d_out;

    void *p_xp, *p_yp, *p_ot, *p_sc, *p_wxt, *p_wyt, *p_wot;
    cudaGetSymbolAddress(&p_xp,  g_xproj);
    cudaGetSymbolAddress(&p_yp,  g_yproj);
    cudaGetSymbolAddress(&p_ot,  g_oprojT);
    cudaGetSymbolAddress(&p_sc,  g_scores);
    cudaGetSymbolAddress(&p_wxt, g_WxT);
    cudaGetSymbolAddress(&p_wyt, g_WyT);
    cudaGetSymbolAddress(&p_wot, g_WoT);
    float* xp  = (float*)p_xp;  float* yp  = (float*)p_yp;
    float* ot  = (float*)p_ot;  float* sc  = (float*)p_sc;
    float* wxt = (float*)p_wxt; float* wyt = (float*)p_wyt; float* wot = (float*)p_wot;

    cudaFuncSetAttribute((const void*)gemm3x<512, 1>,
                         cudaFuncAttributeMaxDynamicSharedMemorySize, SMEM_GEMM_TOTAL);
    cudaFuncSetAttribute((const void*)gemm3x<512, 2>,
                         cudaFuncAttributeMaxDynamicSharedMemorySize, SMEM_GEMM_TOTAL);
    cudaFuncSetAttribute((const void*)gemm3x<256, 0>,
                         cudaFuncAttributeMaxDynamicSharedMemorySize, SMEM_GEMM_TOTAL);
    cudaFuncSetAttribute((const void*)gemm3x<2048, 3>,
                         cudaFuncAttributeMaxDynamicSharedMemorySize, SMEM_GEMM_TOTAL);

    const dim3 tb(32, 8);

    // 1) W transposes: W[512, N] -> WT[N, 512]
    transpose32<<<dim3(CI_ / 32, C_ / 32), tb>>>(Wx, wxt, C_, CI_);
    transpose32<<<dim3(CI_ / 32, C_ / 32), tb>>>(Wy, wyt, C_, CI_);
    transpose32<<<dim3(C_  / 32, C_ / 32), tb>>>(Wo, wot, C_, C_);

    // 2) x_proj, y_proj: [16384,512] @ WT[256,512]^T -> [16384,256], +bias[n]
    gemm3x<512, 1><<<dim3(CI_ / 128, MT_ / 128, 1), 256, SMEM_GEMM_TOTAL>>>(
        inputs, 0, wxt, 0, C_, xp, 0, CI_, bx, 0);
    gemm3x<512, 1><<<dim3(CI_ / 128, MT_ / 128, 1), 256, SMEM_GEMM_TOTAL>>>(
        inputs, 0, wyt, 0, C_, yp, 0, CI_, by, 0);

    // 3) o_proj^T: WoT[512,512] @ inputs[16384,512]^T -> [512,16384], +bias[m]
    gemm3x<512, 2><<<dim3(MT_ / 128, C_ / 128, 1), 256, SMEM_GEMM_TOTAL>>>(
        wot, 0, inputs, 0, C_, ot, 0, MT_, bo, 0);

    // 4) scores[b] = x_proj[b] @ y_proj[b]^T  (batched, K=256)
    gemm3x<256, 0><<<dim3(L_ / 128, L_ / 128, B_), 256, SMEM_GEMM_TOTAL>>>(
        xp, (long long)L_ * CI_, yp, (long long)L_ * CI_, CI_,
        sc, (long long)L_ * L_, L_, nullptr, 0);

    // 5) softmax over batch axis, in place
    softmax_batch<<<(L_ * L_) / 256, 256>>>();

    // 6) out[b] = inputs[b] + attn[b] @ o_proj[b]; B-operand = o_projT slice
    gemm3x<2048, 3><<<dim3(C_ / 128, L_ / 128, B_), 256, SMEM_GEMM_TOTAL>>>(
        sc, (long long)L_ * L_, ot, (long long)L_, MT_,
        out, (long long)L_ * C_, C_, inputs, (long long)L_ * C_);
}

// round 4
// speedup vs baseline: 2.8155x; 1.3270x over previous
#include <cuda_runtime.h>
#include <cuda_bf16.h>
#include <cstdint>
#include <math.h>

// ---------------------------------------------------------------------------
// Problem constants
// ---------------------------------------------------------------------------
#define B_  8
#define L_  2048
#define C_  512
#define CI_ 256
#define MT_ 16384   // B_*L_

typedef __nv_bfloat16 bf16;

// ---------------------------------------------------------------------------
// Scratch (__device__ globals; allocation-free)
// ---------------------------------------------------------------------------
__device__ bf16  g_inH [(size_t)MT_ * C_];           // inputs hi  [bl][c]
__device__ bf16  g_inL [(size_t)MT_ * C_];           // inputs lo
__device__ bf16  g_xpH [(size_t)MT_ * CI_];          // x_proj hi  [bl][i]
__device__ bf16  g_xpL [(size_t)MT_ * CI_];
__device__ bf16  g_ypH [(size_t)MT_ * CI_];
__device__ bf16  g_ypL [(size_t)MT_ * CI_];
__device__ bf16  g_otH [(size_t)C_ * MT_];           // o_proj^T hi [c][bl]
__device__ bf16  g_otL [(size_t)C_ * MT_];
__device__ float g_scores[(size_t)B_ * L_ * L_];     // f32 logits
__device__ bf16  g_atH [(size_t)B_ * L_ * L_];       // attn hi [b][l][m]
__device__ bf16  g_atL [(size_t)B_ * L_ * L_];
__device__ bf16  g_wxtH[CI_ * C_], g_wxtL[CI_ * C_]; // WxT [i][c]
__device__ bf16  g_wytH[CI_ * C_], g_wytL[CI_ * C_];
__device__ bf16  g_wotH[C_ * C_],  g_wotL[C_ * C_];  // WoT [d][c]

// ---------------------------------------------------------------------------
// helpers
// ---------------------------------------------------------------------------
__device__ __forceinline__ uint32_t smem_u32(const void* p) {
    uint32_t a;
    asm("{ .reg .u64 t; cvta.to.shared.u64 t, %1; cvt.u32.u64 %0, t; }"
        : "=r"(a) : "l"(p));
    return a;
}
__device__ __forceinline__ void splitf(float v, bf16& h, bf16& l) {
    h = __float2bfloat16_rn(v);
    l = __float2bfloat16_rn(v - __bfloat162float(h));
}
__device__ __forceinline__ uint32_t pack2(bf16 a, bf16 b) {
    return (uint32_t)__bfloat16_as_ushort(a) |
           ((uint32_t)__bfloat16_as_ushort(b) << 16);
}

#define CP16(dst, src) \
    asm volatile("cp.async.cg.shared.global [%0], [%1], 16;" :: "r"(dst), "l"(src) : "memory")
#define CP_COMMIT() asm volatile("cp.async.commit_group;" ::: "memory")
#define CP_WAIT(n)  asm volatile("cp.async.wait_group %0;" :: "n"(n) : "memory")

#define LDSM_X4(r, a) \
    asm volatile("ldmatrix.sync.aligned.m8n8.x4.shared.b16 {%0,%1,%2,%3}, [%4];" \
        : "=r"((r)[0]), "=r"((r)[1]), "=r"((r)[2]), "=r"((r)[3]) : "r"(a))

__device__ __forceinline__ void mma_bf16(float* d, const uint32_t* a, const uint32_t* b) {
    asm volatile(
        "mma.sync.aligned.m16n8k16.row.col.f32.bf16.bf16.f32 "
        "{%0,%1,%2,%3}, {%4,%5,%6,%7}, {%8,%9}, {%0,%1,%2,%3};"
        : "+f"(d[0]), "+f"(d[1]), "+f"(d[2]), "+f"(d[3])
        : "r"(a[0]), "r"(a[1]), "r"(a[2]), "r"(a[3]), "r"(b[0]), "r"(b[1]));
}

// ---------------------------------------------------------------------------
// 3-term split-bf16 GEMM: D[M,N] = (AH+AL)[M,K] @ (BH+BL)[N,K]^T, K-major.
// Block 128x128, K-chunk 32, 8 warps (4M x 2N), warp tile 32x64.
// SMEM: 4 tiles x (128 rows x 80B) = 40960 B per stage, 2 stages.
// EPI: 0 = f32 store; 1 = +bias[n], write bf16 H/L; 2 = +bias[m], write H/L;
//      3 = +residual(f32), write f32.
// ---------------------------------------------------------------------------
#define ROWB   80u
#define TILE_B 10240u
#define STAGE_B 40960u
#define SMEM_GEMM_TOTAL (2 * 40960)

template<int KTOT, int EPI>
__device__ __forceinline__ void stage_copy(
    uint32_t stage,
    const bf16* __restrict__ AH, const bf16* __restrict__ AL, int ldA, int m0,
    const bf16* __restrict__ BH, const bf16* __restrict__ BL, int ldB, int n0,
    int k0, int tid)
{
    #pragma unroll
    for (int t = 0; t < 4; ++t) {
        const bf16* base = (t == 0) ? AH : (t == 1) ? AL : (t == 2) ? BH : BL;
        const int ld   = (t < 2) ? ldA : ldB;
        const int r0   = (t < 2) ? m0  : n0;
        #pragma unroll
        for (int j = 0; j < 2; ++j) {
            const int seg = tid + 256 * j;        // 0..511
            const int row = seg >> 2;             // 0..127
            const int c   = seg & 3;              // 16B chunk
            const bf16* src = base + (size_t)(r0 + row) * ld + k0 + c * 8;
            const uint32_t dst = stage + t * TILE_B + row * ROWB + c * 16u;
            CP16(dst, src);
        }
    }
}

template<int KTOT, int EPI>
__global__ __launch_bounds__(256, 2) void gemmHL(
    const bf16* __restrict__ AH, const bf16* __restrict__ AL, long long sA, int ldA,
    const bf16* __restrict__ BH, const bf16* __restrict__ BL, long long sB, int ldB,
    float* __restrict__ Cf, bf16* __restrict__ CH, bf16* __restrict__ CL,
    long long sC, int ldC,
    const float* __restrict__ aux, long long sAux)
{
    extern __shared__ char smem[];
    const uint32_t smem_base = smem_u32(smem);

    const int tid  = threadIdx.x;
    const int wid  = tid >> 5;
    const int lane = tid & 31;
    const int g    = lane >> 2;
    const int t4   = lane & 3;
    const int wm   = (wid & 3) * 32;
    const int wn   = (wid >> 2) * 64;

    const int bz = blockIdx.z;
    const int m0 = blockIdx.y * 128;
    const int n0 = blockIdx.x * 128;
    const bf16* aH = AH + (size_t)bz * sA;
    const bf16* aL = AL + (size_t)bz * sA;
    const bf16* bH = BH + (size_t)bz * sB;
    const bf16* bL = BL + (size_t)bz * sB;

    // per-lane ldmatrix base offsets (bytes)
    const uint32_t aoff = (uint32_t)((wm + (lane & 7) + ((lane >> 3) & 1) * 8) * ROWB
                                     + (lane >> 4) * 16);
    const uint32_t boff = (uint32_t)((wn + (lane & 7) + ((lane >> 4) & 1) * 8) * ROWB
                                     + ((lane >> 3) & 1) * 16);

    float acc[2][8][4] = {};
    constexpr int NC = KTOT / 32;

    stage_copy<KTOT, EPI>(smem_base, aH, aL, ldA, m0, bH, bL, ldB, n0, 0, tid);
    CP_COMMIT();
    if (NC > 1) {
        stage_copy<KTOT, EPI>(smem_base + STAGE_B, aH, aL, ldA, m0, bH, bL, ldB, n0, 32, tid);
        CP_COMMIT();
    }

    for (int kc = 0; kc < NC; ++kc) {
        if (kc + 1 < NC) { CP_WAIT(1); } else { CP_WAIT(0); }
        __syncthreads();

        const uint32_t stage = smem_base + (uint32_t)(kc & 1) * STAGE_B;
        #pragma unroll
        for (int ks = 0; ks < 2; ++ks) {
            uint32_t ah[2][4], al[2][4];
            #pragma unroll
            for (int mi = 0; mi < 2; ++mi) {
                LDSM_X4(ah[mi], stage + aoff + mi * 1280u + ks * 32u);
                LDSM_X4(al[mi], stage + TILE_B + aoff + mi * 1280u + ks * 32u);
            }
            #pragma unroll
            for (int h = 0; h < 2; ++h) {
                uint32_t bh[8], bl[8];
                #pragma unroll
                for (int q = 0; q < 2; ++q) {
                    LDSM_X4(bh + q * 4, stage + 2u * TILE_B + boff
                                        + (uint32_t)(h * 32 + q * 16) * ROWB + ks * 32u);
                    LDSM_X4(bl + q * 4, stage + 3u * TILE_B + boff
                                        + (uint32_t)(h * 32 + q * 16) * ROWB + ks * 32u);
                }
                #pragma unroll
                for (int njl = 0; njl < 4; ++njl) {
                    const int nj = h * 4 + njl;
                    const uint32_t* bhf = bh + njl * 2;
                    const uint32_t* blf = bl + njl * 2;
                    #pragma unroll
                    for (int mi = 0; mi < 2; ++mi) {
                        mma_bf16(acc[mi][nj], ah[mi], bhf);
                        mma_bf16(acc[mi][nj], ah[mi], blf);
                        mma_bf16(acc[mi][nj], al[mi], bhf);
                    }
                }
            }
        }

        if (kc + 2 < NC) {
            __syncthreads();
            stage_copy<KTOT, EPI>(stage, aH, aL, ldA, m0, bH, bL, ldB, n0,
                                  (kc + 2) * 32, tid);
            CP_COMMIT();
        }
    }

    // ---- epilogue ----
    float biasr[4];
    if (EPI == 2) {
        #pragma unroll
        for (int mi = 0; mi < 2; ++mi) {
            biasr[mi * 2 + 0] = aux[m0 + wm + mi * 16 + g    ];
            biasr[mi * 2 + 1] = aux[m0 + wm + mi * 16 + g + 8];
        }
    }
    const float* R = (EPI == 3) ? (aux + (size_t)bz * sAux) : nullptr;
    float* Cfb = (EPI == 0 || EPI == 3) ? (Cf + (size_t)bz * sC) : nullptr;
    bf16* CHb = (EPI == 1 || EPI == 2) ? (CH + (size_t)bz * sC) : nullptr;
    bf16* CLb = (EPI == 1 || EPI == 2) ? (CL + (size_t)bz * sC) : nullptr;

    #pragma unroll
    for (int mi = 0; mi < 2; ++mi) {
        const int r0 = m0 + wm + mi * 16 + g;
        const int r1 = r0 + 8;
        #pragma unroll
        for (int nj = 0; nj < 8; ++nj) {
            const int col = n0 + wn + nj * 8 + 2 * t4;
            float2 v0 = make_float2(acc[mi][nj][0], acc[mi][nj][1]);
            float2 v1 = make_float2(acc[mi][nj][2], acc[mi][nj][3]);
            if (EPI == 1) {
                const float2 bb = *(const float2*)&aux[col];
                v0.x += bb.x; v0.y += bb.y; v1.x += bb.x; v1.y += bb.y;
            } else if (EPI == 2) {
                v0.x += biasr[mi * 2];     v0.y += biasr[mi * 2];
                v1.x += biasr[mi * 2 + 1]; v1.y += biasr[mi * 2 + 1];
            } else if (EPI == 3) {
                const float2 q0 = *(const float2*)&R[(size_t)r0 * ldC + col];
                const float2 q1 = *(const float2*)&R[(size_t)r1 * ldC + col];
                v0.x += q0.x; v0.y += q0.y; v1.x += q1.x; v1.y += q1.y;
            }
            if (EPI == 0 || EPI == 3) {
                *(float2*)&Cfb[(size_t)r0 * ldC + col] = v0;
                *(float2*)&Cfb[(size_t)r1 * ldC + col] = v1;
            } else {
                bf16 h0, l0, h1, l1;
                splitf(v0.x, h0, l0); splitf(v0.y, h1, l1);
                *(uint32_t*)&CHb[(size_t)r0 * ldC + col] = pack2(h0, h1);
                *(uint32_t*)&CLb[(size_t)r0 * ldC + col] = pack2(l0, l1);
                splitf(v1.x, h0, l0); splitf(v1.y, h1, l1);
                *(uint32_t*)&CHb[(size_t)r1 * ldC + col] = pack2(h0, h1);
                *(uint32_t*)&CLb[(size_t)r1 * ldC + col] = pack2(l0, l1);
            }
        }
    }
}

// ---------------------------------------------------------------------------
// Decompose inputs f32 -> bf16 hi/lo (vectorized)
// ---------------------------------------------------------------------------
__global__ __launch_bounds__(256) void decomp_inputs(const float* __restrict__ src, int n4)
{
    const int i = blockIdx.x * 256 + threadIdx.x;
    if (i >= n4) return;
    const float4 v = ((const float4*)src)[i];
    bf16 h0, h1, h2, h3, l0, l1, l2, l3;
    splitf(v.x, h0, l0); splitf(v.y, h1, l1);
    splitf(v.z, h2, l2); splitf(v.w, h3, l3);
    ((uint2*)g_inH)[i] = make_uint2(pack2(h0, h1), pack2(h2, h3));
    ((uint2*)g_inL)[i] = make_uint2(pack2(l0, l1), pack2(l2, l3));
}

// ---------------------------------------------------------------------------
// Transpose + decompose weights: src[R][Cc] f32 -> H/L[Cc][R] bf16
// ---------------------------------------------------------------------------
__global__ void transposeHL(const float* __restrict__ src,
                            bf16* __restrict__ H, bf16* __restrict__ L,
                            int R, int Cc)
{
    __shared__ float tbuf[32][33];
    const int bx = blockIdx.x * 32;
    const int by = blockIdx.y * 32;
    const int x = threadIdx.x, y = threadIdx.y;   // 32 x 8
    #pragma unroll
    for (int d = 0; d < 32; d += 8)
        tbuf[y + d][x] = src[(size_t)(by + y + d) * Cc + bx + x];
    __syncthreads();
    #pragma unroll
    for (int d = 0; d < 32; d += 8) {
        bf16 h, l;
        splitf(tbuf[x][y + d], h, l);
        H[(size_t)(bx + y + d) * R + by + x] = h;
        L[(size_t)(bx + y + d) * R + by + x] = l;
    }
}

// ---------------------------------------------------------------------------
// Softmax over batch axis, f32 logits -> bf16 hi/lo attn
// ---------------------------------------------------------------------------
__global__ __launch_bounds__(256) void softmax_batch_HL()
{
    const size_t idx = ((size_t)blockIdx.x * 256 + threadIdx.x) * 2;  // pairs
    const size_t stride = (size_t)L_ * L_;
    float v0[B_], v1[B_];
    float mx0 = -INFINITY, mx1 = -INFINITY;
    #pragma unroll
    for (int b = 0; b < B_; ++b) {
        const float2 p = *(const float2*)&g_scores[b * stride + idx];
        v0[b] = p.x; v1[b] = p.y;
        mx0 = fmaxf(mx0, p.x); mx1 = fmaxf(mx1, p.y);
    }
    float s0 = 0.f, s1 = 0.f;
    #pragma unroll
    for (int b = 0; b < B_; ++b) {
        v0[b] = expf(v0[b] - mx0); s0 += v0[b];
        v1[b] = expf(v1[b] - mx1); s1 += v1[b];
    }
    const float i0 = 1.f / s0, i1 = 1.f / s1;
    #pragma unroll
    for (int b = 0; b < B_; ++b) {
        bf16 h0, l0, h1, l1;
        splitf(v0[b] * i0, h0, l0);
        splitf(v1[b] * i1, h1, l1);
        *(uint32_t*)&g_atH[b * stride + idx] = pack2(h0, h1);
        *(uint32_t*)&g_atL[b * stride + idx] = pack2(l0, l1);
    }
}

// ---------------------------------------------------------------------------
// Launch: inputs, Wx, bx, Wy, by, Wo, bo
// ---------------------------------------------------------------------------
extern "C" void kernel_launch(void* const* d_in, const int* in_sizes, int n_in,
                              void* d_out, int out_size)
{
    const float* inputs = (const float*)d_in[0];
    const float* Wx = (const float*)d_in[1];
    const float* bx = (const float*)d_in[2];
    const float* Wy = (const float*)d_in[3];
    const float* by = (const float*)d_in[4];
    const float* Wo = (const float*)d_in[5];
    const float* bo = (const float*)d_in[6];
    float* out = (float*)d_out;

    // symbol addresses
    void *a;
    bf16 *inH, *inL, *xpH, *xpL, *ypH, *ypL, *otH, *otL, *atH, *atL;
    bf16 *wxtH, *wxtL, *wytH, *wytL, *wotH, *wotL;
    float *sc;
    cudaGetSymbolAddress(&a, g_inH);  inH  = (bf16*)a;
    cudaGetSymbolAddress(&a, g_inL);  inL  = (bf16*)a;
    cudaGetSymbolAddress(&a, g_xpH);  xpH  = (bf16*)a;
    cudaGetSymbolAddress(&a, g_xpL);  xpL  = (bf16*)a;
    cudaGetSymbolAddress(&a, g_ypH);  ypH  = (bf16*)a;
    cudaGetSymbolAddress(&a, g_ypL);  ypL  = (bf16*)a;
    cudaGetSymbolAddress(&a, g_otH);  otH  = (bf16*)a;
    cudaGetSymbolAddress(&a, g_otL);  otL  = (bf16*)a;
    cudaGetSymbolAddress(&a, g_atH);  atH  = (bf16*)a;
    cudaGetSymbolAddress(&a, g_atL);  atL  = (bf16*)a;
    cudaGetSymbolAddress(&a, g_wxtH); wxtH = (bf16*)a;
    cudaGetSymbolAddress(&a, g_wxtL); wxtL = (bf16*)a;
    cudaGetSymbolAddress(&a, g_wytH); wytH = (bf16*)a;
    cudaGetSymbolAddress(&a, g_wytL); wytL = (bf16*)a;
    cudaGetSymbolAddress(&a, g_wotH); wotH = (bf16*)a;
    cudaGetSymbolAddress(&a, g_wotL); wotL = (bf16*)a;
    cudaGetSymbolAddress(&a, g_scores); sc = (float*)a;

    cudaFuncSetAttribute((const void*)gemmHL<512, 1>,
                         cudaFuncAttributeMaxDynamicSharedMemorySize, SMEM_GEMM_TOTAL);
    cudaFuncSetAttribute((const void*)gemmHL<512, 2>,
                         cudaFuncAttributeMaxDynamicSharedMemorySize, SMEM_GEMM_TOTAL);
    cudaFuncSetAttribute((const void*)gemmHL<256, 0>,
                         cudaFuncAttributeMaxDynamicSharedMemorySize, SMEM_GEMM_TOTAL);
    cudaFuncSetAttribute((const void*)gemmHL<2048, 3>,
                         cudaFuncAttributeMaxDynamicSharedMemorySize, SMEM_GEMM_TOTAL);

    // 0) decompose inputs + weights
    decomp_inputs<<<(MT_ * C_ / 4 + 255) / 256, 256>>>(inputs, MT_ * C_ / 4);
    const dim3 tb(32, 8);
    transposeHL<<<dim3(CI_ / 32, C_ / 32), tb>>>(Wx, wxtH, wxtL, C_, CI_);
    transposeHL<<<dim3(CI_ / 32, C_ / 32), tb>>>(Wy, wytH, wytL, C_, CI_);
    transposeHL<<<dim3(C_  / 32, C_ / 32), tb>>>(Wo, wotH, wotL, C_, C_);

    // 1) x_proj, y_proj: in[16384,512] @ WT[256,512]^T  (+bias[n], HL out)
    gemmHL<512, 1><<<dim3(CI_ / 128, MT_ / 128, 1), 256, SMEM_GEMM_TOTAL>>>(
        inH, inL, 0, C_, wxtH, wxtL, 0, C_,
        nullptr, xpH, xpL, 0, CI_, bx, 0);
    gemmHL<512, 1><<<dim3(CI_ / 128, MT_ / 128, 1), 256, SMEM_GEMM_TOTAL>>>(
        inH, inL, 0, C_, wytH, wytL, 0, C_,
        nullptr, ypH, ypL, 0, CI_, by, 0);

    // 2) o_proj^T: WoT[512,512] @ in[16384,512]^T  (+bias[m], HL out)
    gemmHL<512, 2><<<dim3(MT_ / 128, C_ / 128, 1), 256, SMEM_GEMM_TOTAL>>>(
        wotH, wotL, 0, C_, inH, inL, 0, C_,
        nullptr, otH, otL, 0, MT_, bo, 0);

    // 3) scores[b] = x_proj[b] @ y_proj[b]^T  (f32 out)
    gemmHL<256, 0><<<dim3(L_ / 128, L_ / 128, B_), 256, SMEM_GEMM_TOTAL>>>(
        xpH, xpL, (long long)L_ * CI_, CI_, ypH, ypL, (long long)L_ * CI_, CI_,
        sc, nullptr, nullptr, (long long)L_ * L_, L_, nullptr, 0);

    // 4) softmax over batch -> attn HL
    softmax_batch_HL<<<(L_ * L_ / 2) / 256, 256>>>();

    // 5) out[b] = inputs[b] + attn[b] @ o_proj[b]
    gemmHL<2048, 3><<<dim3(C_ / 128, L_ / 128, B_), 256, SMEM_GEMM_TOTAL>>>(
        atH, atL, (long long)L_ * L_, L_, otH, otL, (long long)L_, MT_,
        out, nullptr, nullptr, (long long)L_ * C_, C_, inputs, (long long)L_ * C_);
}